// round 1
// baseline (speedup 1.0000x reference)
#include <cuda_runtime.h>
#include <cuda_bf16.h>
#include <math.h>

// ---------------------------------------------------------------------------
// CortexBlock: qkv proj -> alpha -> sequential fast-weight scan -> out proj
// B=4, T=2048, D=1024, H=16, Dh=64, R=16
// ---------------------------------------------------------------------------

#define D_MODEL 1024
#define N_HEADS 16
#define D_HEAD  64
#define RANK    16
#define DECAY   0.95f
#define ALPHA_MAX 0.05f
#define BETA    0.01f

#define BB 4
#define TT 2048
#define BT (BB*TT)   // 8192

// Scratch (static device globals: allocation-free rule)
__device__ float g_q[BT * D_MODEL];
__device__ float g_k[BT * D_MODEL];
__device__ float g_v[BT * D_MODEL];
__device__ float g_y[BT * D_MODEL];
__device__ float g_alpha[BT * N_HEADS];

// ---------------------------------------------------------------------------
// SGEMM (NT): C[M,N] = A[M,K] * B[N,K]^T, all row-major, fp32.
// Tiles: 128x64x16, 256 threads, 8x4 per thread.
// ---------------------------------------------------------------------------
#define GBM 128
#define GBN 64
#define GBK 16

__global__ __launch_bounds__(256) void sgemm_nt(
    const float* __restrict__ A, const float* __restrict__ B,
    float* __restrict__ C, int M, int N, int K)
{
    __shared__ float As[GBK][GBM];
    __shared__ float Bs[GBK][GBN];

    const int tid = threadIdx.x;
    const int tx = tid & 15;    // N direction (16)
    const int ty = tid >> 4;    // M direction (16)
    const int rowBase = blockIdx.y * GBM;
    const int colBase = blockIdx.x * GBN;

    float acc[8][4];
#pragma unroll
    for (int i = 0; i < 8; i++)
#pragma unroll
        for (int j = 0; j < 4; j++) acc[i][j] = 0.0f;

    for (int k0 = 0; k0 < K; k0 += GBK) {
        // Load A tile: 128 rows x 16 k  = 512 float4, 2 per thread
#pragma unroll
        for (int i = 0; i < 2; i++) {
            int L = tid + i * 256;
            int row = L >> 2;
            int kq  = (L & 3) << 2;
            float4 va = *reinterpret_cast<const float4*>(
                A + (size_t)(rowBase + row) * K + k0 + kq);
            As[kq + 0][row] = va.x;
            As[kq + 1][row] = va.y;
            As[kq + 2][row] = va.z;
            As[kq + 3][row] = va.w;
        }
        // Load B tile: 64 rows x 16 k = 256 float4, 1 per thread
        {
            int L = tid;
            int n  = L >> 2;
            int kq = (L & 3) << 2;
            float4 vb = *reinterpret_cast<const float4*>(
                B + (size_t)(colBase + n) * K + k0 + kq);
            Bs[kq + 0][n] = vb.x;
            Bs[kq + 1][n] = vb.y;
            Bs[kq + 2][n] = vb.z;
            Bs[kq + 3][n] = vb.w;
        }
        __syncthreads();

#pragma unroll
        for (int kk = 0; kk < GBK; kk++) {
            float4 a0 = *reinterpret_cast<const float4*>(&As[kk][ty * 8]);
            float4 a1 = *reinterpret_cast<const float4*>(&As[kk][ty * 8 + 4]);
            float4 b0 = *reinterpret_cast<const float4*>(&Bs[kk][tx * 4]);
            float a[8] = {a0.x, a0.y, a0.z, a0.w, a1.x, a1.y, a1.z, a1.w};
            float b[4] = {b0.x, b0.y, b0.z, b0.w};
#pragma unroll
            for (int i = 0; i < 8; i++)
#pragma unroll
                for (int j = 0; j < 4; j++)
                    acc[i][j] = fmaf(a[i], b[j], acc[i][j]);
        }
        __syncthreads();
    }

    // Epilogue
#pragma unroll
    for (int i = 0; i < 8; i++) {
        float4 out = make_float4(acc[i][0], acc[i][1], acc[i][2], acc[i][3]);
        *reinterpret_cast<float4*>(
            C + (size_t)(rowBase + ty * 8 + i) * N + colBase + tx * 4) = out;
    }
}

// ---------------------------------------------------------------------------
// alpha[row,h] = min( sigmoid(x[row]·Wa[h] + ba[h]) * m_gate[row] * as[row,h],
//                    ALPHA_MAX )
// One block per row (b*T+t), 256 threads = 8 warps, each warp does 2 heads.
// ---------------------------------------------------------------------------
__global__ __launch_bounds__(256) void alpha_kernel(
    const float* __restrict__ x, const float* __restrict__ Wa,
    const float* __restrict__ ba, const float* __restrict__ m_gate,
    const float* __restrict__ ascale, float* __restrict__ alpha)
{
    const int row = blockIdx.x;
    const int tid = threadIdx.x;
    const int warp = tid >> 5;
    const int lane = tid & 31;

    __shared__ float4 xs[D_MODEL / 4];
    const float4* xg = reinterpret_cast<const float4*>(x + (size_t)row * D_MODEL);
    for (int i = tid; i < D_MODEL / 4; i += 256) xs[i] = xg[i];
    __syncthreads();

    const float mg = m_gate[row];
#pragma unroll
    for (int hh = 0; hh < 2; hh++) {
        int h = warp + hh * 8;
        const float4* w = reinterpret_cast<const float4*>(Wa + (size_t)h * D_MODEL);
        float s = 0.0f;
        for (int i = lane; i < D_MODEL / 4; i += 32) {
            float4 xv = xs[i];
            float4 wv = w[i];
            s = fmaf(xv.x, wv.x, s);
            s = fmaf(xv.y, wv.y, s);
            s = fmaf(xv.z, wv.z, s);
            s = fmaf(xv.w, wv.w, s);
        }
#pragma unroll
        for (int off = 16; off; off >>= 1)
            s += __shfl_xor_sync(0xFFFFFFFFu, s, off);
        if (lane == 0) {
            float z = s + ba[h];
            float sg = 1.0f / (1.0f + expf(-z));
            float a = sg * mg * ascale[(size_t)row * N_HEADS + h];
            alpha[(size_t)row * N_HEADS + h] = fminf(a, ALPHA_MAX);
        }
    }
}

// ---------------------------------------------------------------------------
// Sequential fast-weight scan. Block = (b,h); 64 threads, thread = d.
// Thread d owns U[d][0..15] and V[0..15][d] in registers.
// k_fast[d] = sum_r U[d][r]*V[r][d] is thread-local; only ku[16] and the two
// scores need cross-thread (64-lane) reduction: intra-warp butterfly + smem.
// ---------------------------------------------------------------------------
__global__ __launch_bounds__(64) void scan_kernel(
    const float* __restrict__ q, const float* __restrict__ k,
    const float* __restrict__ v, const float* __restrict__ alpha,
    float* __restrict__ y, int T)
{
    const int bh = blockIdx.x;          // b*H + h
    const int b = bh / N_HEADS;
    const int h = bh % N_HEADS;
    const int d = threadIdx.x;          // 0..63
    const int warp = d >> 5;
    const int lane = d & 31;

    float U[RANK], Vv[RANK];
#pragma unroll
    for (int r = 0; r < RANK; r++) { U[r] = 0.0f; Vv[r] = 0.0f; }

    __shared__ float red[2][18];

    const size_t base = ((size_t)b * T * N_HEADS + h) * D_HEAD + d;
    const size_t strideT = (size_t)N_HEADS * D_HEAD;   // 1024
    const size_t abase = (size_t)b * T * N_HEADS + h;

    const float inv_sqrt_dh = 0.125f;   // 1/sqrt(64)

    for (int t = 0; t < T; t++) {
        const size_t idx = base + (size_t)t * strideT;
        const float qt = q[idx];
        const float kt = k[idx];
        const float vt = v[idx];
        const float a  = alpha[abase + (size_t)t * N_HEADS];

        // decay + partials for ku
        float p[RANK];
#pragma unroll
        for (int r = 0; r < RANK; r++) {
            U[r]  *= DECAY;
            Vv[r] *= DECAY;
            p[r] = kt * U[r];
        }
        // reduce p over 64 threads: intra-warp butterfly
#pragma unroll
        for (int off = 16; off; off >>= 1)
#pragma unroll
            for (int r = 0; r < RANK; r++)
                p[r] += __shfl_xor_sync(0xFFFFFFFFu, p[r], off);
        if (lane == 0) {
#pragma unroll
            for (int r = 0; r < RANK; r++) red[warp][r] = p[r];
        }
        __syncthreads();
        float ku[RANK];
#pragma unroll
        for (int r = 0; r < RANK; r++) ku[r] = red[0][r] + red[1][r];
        __syncthreads();   // protect red[0..15] before next phase reuse

        const float ak = a * kt;
        const float av = a * vt;
        float kf = 0.0f;
#pragma unroll
        for (int r = 0; r < RANK; r++) {
            float u = fmaf(ak, ku[r], U[r]);
            float w = fmaf(av, ku[r], Vv[r]);
            u -= BETA * fminf(fmaxf(u, -1.0f), 1.0f);
            w -= BETA * fminf(fmaxf(w, -1.0f), 1.0f);
            U[r] = u;
            Vv[r] = w;
            kf = fmaf(u, w, kf);
        }

        const float qn = qt * inv_sqrt_dh;
        float s0 = qn * kt;
        float s1 = qn * kf;
#pragma unroll
        for (int off = 16; off; off >>= 1) {
            s0 += __shfl_xor_sync(0xFFFFFFFFu, s0, off);
            s1 += __shfl_xor_sync(0xFFFFFFFFu, s1, off);
        }
        if (lane == 0) { red[warp][16] = s0; red[warp][17] = s1; }
        __syncthreads();
        s0 = red[0][16] + red[1][16];
        s1 = red[0][17] + red[1][17];

        // softmax over {s0, s1}; mix_logit[h] cancels (added to both)
        const float m1 = 1.0f / (1.0f + expf(s0 - s1));
        const float m0 = 1.0f - m1;

        y[idx] = m0 * vt + m1 * kf;
    }
}

// ---------------------------------------------------------------------------
// Launch
// ---------------------------------------------------------------------------
extern "C" void kernel_launch(void* const* d_in, const int* in_sizes, int n_in,
                              void* d_out, int out_size)
{
    const float* x      = (const float*)d_in[0];  // [B,T,1024]
    const float* m_gate = (const float*)d_in[1];  // [B,T]
    const float* ascale = (const float*)d_in[2];  // [B,T,16]
    const float* Wq     = (const float*)d_in[3];
    const float* Wk     = (const float*)d_in[4];
    const float* Wv     = (const float*)d_in[5];
    const float* Wo     = (const float*)d_in[6];
    const float* Wa     = (const float*)d_in[7];  // [16,1024]
    const float* ba     = (const float*)d_in[8];  // [16]
    // d_in[9] = mix_logit: cancels in the 2-way softmax, unused.
    float* out = (float*)d_out;

    const int M = in_sizes[1];          // B*T = 8192
    const int T = M / BB;               // 2048

    float *dq, *dk, *dv, *dy, *da;
    cudaGetSymbolAddress((void**)&dq, g_q);
    cudaGetSymbolAddress((void**)&dk, g_k);
    cudaGetSymbolAddress((void**)&dv, g_v);
    cudaGetSymbolAddress((void**)&dy, g_y);
    cudaGetSymbolAddress((void**)&da, g_alpha);

    dim3 gblk(D_MODEL / GBN, M / GBM);  // (16, 64)

    sgemm_nt<<<gblk, 256>>>(x, Wq, dq, M, D_MODEL, D_MODEL);
    sgemm_nt<<<gblk, 256>>>(x, Wk, dk, M, D_MODEL, D_MODEL);
    sgemm_nt<<<gblk, 256>>>(x, Wv, dv, M, D_MODEL, D_MODEL);

    alpha_kernel<<<M, 256>>>(x, Wa, ba, m_gate, ascale, da);

    scan_kernel<<<BB * N_HEADS, 64>>>(dq, dk, dv, da, dy, T);

    sgemm_nt<<<gblk, 256>>>(dy, Wo, out, M, D_MODEL, D_MODEL);
}

// round 3
// speedup vs baseline: 2.2131x; 2.2131x over previous
#include <cuda_runtime.h>
#include <cuda_bf16.h>
#include <math.h>
#include <stdint.h>

// ---------------------------------------------------------------------------
// CortexBlock on GB300 (compute_103 pipeline => no tcgen05; use mma.sync HMMA)
// B=4, T=2048, D=1024, H=16, Dh=64, R=16
// GEMMs: bf16x2 error-compensated (hi*hi + hi*lo + lo*hi), fp32 accumulate.
// ---------------------------------------------------------------------------

#define D_MODEL 1024
#define N_HEADS 16
#define D_HEAD  64
#define RANK    16
#define DECAY   0.95f
#define ALPHA_MAX 0.05f
#define BETA    0.01f

#define BB 4
#define TT 2048
#define BT (BB*TT)   // 8192

// ---------------- scratch (static device globals; no allocs allowed) -------
__device__ __align__(256) __nv_bfloat16 g_xhi[BT * D_MODEL];
__device__ __align__(256) __nv_bfloat16 g_xlo[BT * D_MODEL];
__device__ __align__(256) __nv_bfloat16 g_whi[4 * D_MODEL * D_MODEL];  // Wq,Wk,Wv,Wo
__device__ __align__(256) __nv_bfloat16 g_wlo[4 * D_MODEL * D_MODEL];
__device__ __align__(256) __nv_bfloat16 g_yhi[BT * D_MODEL];
__device__ __align__(256) __nv_bfloat16 g_ylo[BT * D_MODEL];
__device__ __align__(256) float g_q[BT * D_MODEL];
__device__ __align__(256) float g_k[BT * D_MODEL];
__device__ __align__(256) float g_v[BT * D_MODEL];
__device__ __align__(256) float g_alpha[BT * N_HEADS];

// ---------------- small asm helpers ----------------------------------------
__device__ __forceinline__ uint32_t smem_u32(const void* p) {
    uint32_t a;
    asm("{ .reg .u64 t; cvta.to.shared.u64 t, %1; cvt.u32.u64 %0, t; }"
        : "=r"(a) : "l"(p));
    return a;
}
__device__ __forceinline__ void cp_async16(uint32_t daddr, const void* gaddr) {
    asm volatile("cp.async.cg.shared.global [%0], [%1], 16;"
                 :: "r"(daddr), "l"(gaddr) : "memory");
}
#define CP_COMMIT()  asm volatile("cp.async.commit_group;" ::: "memory")
#define CP_WAIT(n)   asm volatile("cp.async.wait_group %0;" :: "n"(n) : "memory")

__device__ __forceinline__ void ldsm_x4(uint32_t (&r)[4], uint32_t addr) {
    asm volatile("ldmatrix.sync.aligned.m8n8.x4.shared.b16 {%0,%1,%2,%3}, [%4];"
                 : "=r"(r[0]), "=r"(r[1]), "=r"(r[2]), "=r"(r[3]) : "r"(addr));
}
__device__ __forceinline__ void mma_16816(float (&d)[4], const uint32_t (&a)[4],
                                          uint32_t b0, uint32_t b1) {
    asm volatile(
        "mma.sync.aligned.m16n8k16.row.col.f32.bf16.bf16.f32 "
        "{%0,%1,%2,%3}, {%4,%5,%6,%7}, {%8,%9}, {%0,%1,%2,%3};"
        : "+f"(d[0]), "+f"(d[1]), "+f"(d[2]), "+f"(d[3])
        : "r"(a[0]), "r"(a[1]), "r"(a[2]), "r"(a[3]), "r"(b0), "r"(b1));
}

// ---------------------------------------------------------------------------
// bf16x2 GEMM: C[M,N](fp32) = Ahi*Bhi^T + Ahi*Blo^T + Alo*Bhi^T
// A[M,K], B[N,K] row-major bf16.  CTA tile 128x128, K-chunk 64.
// 8 warps = 2(m) x 4(n) of 64x32 warp tiles.  cp.async double-buffered.
// smem stride 72 halves (144B): conflict-free ldmatrix (144 mod 128 = 16).
// ---------------------------------------------------------------------------
#define GM 128
#define GN 128
#define GKC 64
#define AST 72                      // halves per smem row
#define TILE_HALVES (GM * AST)      // 9216 halves = 18432 B per tile buffer

__global__ __launch_bounds__(256, 2) void gemm_bf16x2(
    const __nv_bfloat16* __restrict__ Ahi, const __nv_bfloat16* __restrict__ Alo,
    const __nv_bfloat16* __restrict__ Bhi, const __nv_bfloat16* __restrict__ Blo,
    float* __restrict__ C, int M, int N, int K)
{
    extern __shared__ __nv_bfloat16 smem[];
    __nv_bfloat16* sA = smem;                     // [2][TILE_HALVES]
    __nv_bfloat16* sB = smem + 2 * TILE_HALVES;   // [2][TILE_HALVES]

    const int tid  = threadIdx.x;
    const int wid  = tid >> 5;
    const int lane = tid & 31;
    const int rowBase = blockIdx.y * GM;
    const int colBase = blockIdx.x * GN;

    const int wm = (wid >> 2) * 64;   // warp m offset: 0 / 64
    const int wn = (wid & 3) * 32;    // warp n offset: 0/32/64/96

    const uint32_t sA_addr = smem_u32(sA);
    const uint32_t sB_addr = smem_u32(sB);
    const uint32_t TILE_B = TILE_HALVES * 2;   // bytes

    const int NPP = K / GKC;          // chunks per pass (16)
    const int NCH = 3 * NPP;          // 48

    float acc[4][4][4];
#pragma unroll
    for (int i = 0; i < 4; i++)
#pragma unroll
        for (int j = 0; j < 4; j++)
#pragma unroll
            for (int c = 0; c < 4; c++) acc[i][j][c] = 0.0f;

    // per-lane ldmatrix address components
    const int aRow = lane & 15;              // A: lanes 0-15 rows 0-15 (k lo), 16-31 same rows (k hi)
    const int aKo  = (lane >> 4) * 8;
    const int bNo  = ((lane >> 4) << 3) + (lane & 7);  // B: n offset
    const int bKo  = ((lane >> 3) & 1) * 8;            // B: k offset

    // ---- cp.async tile loader ----
    auto issue = [&](int ci, int buf) {
        const int pass = ci / NPP;
        const int kc   = ci % NPP;
        const int k0   = kc * GKC;
        const __nv_bfloat16* Asrc = (pass == 2) ? Alo : Ahi;
        const __nv_bfloat16* Bsrc = (pass == 1) ? Blo : Bhi;
#pragma unroll
        for (int i = 0; i < 4; i++) {
            int L = tid + (i << 8);          // 0..1023
            int row = L >> 3;
            int seg = L & 7;                 // 16B segment (8 halves)
            uint32_t off = (uint32_t)buf * TILE_B + row * (AST * 2) + seg * 16;
            cp_async16(sA_addr + off,
                       Asrc + (size_t)(rowBase + row) * K + k0 + seg * 8);
            cp_async16(sB_addr + off,
                       Bsrc + (size_t)(colBase + row) * K + k0 + seg * 8);
        }
        CP_COMMIT();
    };

    issue(0, 0);

    for (int ci = 0; ci < NCH; ci++) {
        const int buf = ci & 1;
        if (ci + 1 < NCH) {
            issue(ci + 1, buf ^ 1);
            CP_WAIT(1);
        } else {
            CP_WAIT(0);
        }
        __syncthreads();

        const uint32_t aBase = sA_addr + (uint32_t)buf * TILE_B;
        const uint32_t bBase = sB_addr + (uint32_t)buf * TILE_B;

#pragma unroll
        for (int ks = 0; ks < 4; ks++) {     // 4 x k16 per 64 chunk
            uint32_t Ar[4][4];
#pragma unroll
            for (int mi = 0; mi < 4; mi++) {
                uint32_t addr = aBase + (uint32_t)(wm + mi * 16 + aRow) * (AST * 2)
                              + (uint32_t)(ks * 16 + aKo) * 2;
                ldsm_x4(Ar[mi], addr);
            }
            uint32_t Br[2][4];
#pragma unroll
            for (int ni = 0; ni < 2; ni++) {
                uint32_t addr = bBase + (uint32_t)(wn + ni * 16 + bNo) * (AST * 2)
                              + (uint32_t)(ks * 16 + bKo) * 2;
                ldsm_x4(Br[ni], addr);
            }
#pragma unroll
            for (int mi = 0; mi < 4; mi++)
#pragma unroll
                for (int j = 0; j < 4; j++)
                    mma_16816(acc[mi][j], Ar[mi],
                              Br[j >> 1][(j & 1) * 2], Br[j >> 1][(j & 1) * 2 + 1]);
        }
        __syncthreads();
    }

    // ---- epilogue: c frag -> fp32 C (float2 stores) ----
#pragma unroll
    for (int mi = 0; mi < 4; mi++) {
        const int row0 = rowBase + wm + mi * 16 + (lane >> 2);
#pragma unroll
        for (int j = 0; j < 4; j++) {
            const int col = colBase + wn + j * 8 + (lane & 3) * 2;
            *reinterpret_cast<float2*>(C + (size_t)row0 * N + col) =
                make_float2(acc[mi][j][0], acc[mi][j][1]);
            *reinterpret_cast<float2*>(C + (size_t)(row0 + 8) * N + col) =
                make_float2(acc[mi][j][2], acc[mi][j][3]);
        }
    }
}

// ---------------------------------------------------------------------------
// fp32 -> (bf16 hi, bf16 lo)
// ---------------------------------------------------------------------------
__global__ __launch_bounds__(256) void split_kernel(
    const float* __restrict__ in, __nv_bfloat16* __restrict__ hi,
    __nv_bfloat16* __restrict__ lo, int n)
{
    int i = blockIdx.x * blockDim.x + threadIdx.x;
    if (i < n) {
        float x = in[i];
        __nv_bfloat16 h = __float2bfloat16(x);
        hi[i] = h;
        lo[i] = __float2bfloat16(x - __bfloat162float(h));
    }
}

// ---------------------------------------------------------------------------
// alpha[row,h] = min( sigmoid(x·Wa[h]+ba[h]) * m_gate * as, ALPHA_MAX )
// ---------------------------------------------------------------------------
__global__ __launch_bounds__(256) void alpha_kernel(
    const float* __restrict__ x, const float* __restrict__ Wa,
    const float* __restrict__ ba, const float* __restrict__ m_gate,
    const float* __restrict__ ascale, float* __restrict__ alpha)
{
    const int row = blockIdx.x;
    const int tid = threadIdx.x;
    const int warp = tid >> 5;
    const int lane = tid & 31;

    __shared__ float4 xs[D_MODEL / 4];
    const float4* xg = reinterpret_cast<const float4*>(x + (size_t)row * D_MODEL);
    for (int i = tid; i < D_MODEL / 4; i += 256) xs[i] = xg[i];
    __syncthreads();

    const float mg = m_gate[row];
#pragma unroll
    for (int hh = 0; hh < 2; hh++) {
        int h = warp + hh * 8;
        const float4* w = reinterpret_cast<const float4*>(Wa + (size_t)h * D_MODEL);
        float s = 0.0f;
        for (int i = lane; i < D_MODEL / 4; i += 32) {
            float4 xv = xs[i];
            float4 wv = w[i];
            s = fmaf(xv.x, wv.x, s);
            s = fmaf(xv.y, wv.y, s);
            s = fmaf(xv.z, wv.z, s);
            s = fmaf(xv.w, wv.w, s);
        }
#pragma unroll
        for (int off = 16; off; off >>= 1)
            s += __shfl_xor_sync(0xFFFFFFFFu, s, off);
        if (lane == 0) {
            float z = s + ba[h];
            float sg = 1.0f / (1.0f + expf(-z));
            float a = sg * mg * ascale[(size_t)row * N_HEADS + h];
            alpha[(size_t)row * N_HEADS + h] = fminf(a, ALPHA_MAX);
        }
    }
}

// ---------------------------------------------------------------------------
// Sequential fast-weight scan; fused y -> bf16x2 output; next-step prefetch.
// Block = (b,h); 64 threads (thread = d).
// ---------------------------------------------------------------------------
__global__ __launch_bounds__(64) void scan_kernel(
    const float* __restrict__ q, const float* __restrict__ k,
    const float* __restrict__ v, const float* __restrict__ alpha,
    __nv_bfloat16* __restrict__ yhi, __nv_bfloat16* __restrict__ ylo, int T)
{
    const int bh = blockIdx.x;
    const int b = bh / N_HEADS;
    const int h = bh % N_HEADS;
    const int d = threadIdx.x;
    const int warp = d >> 5;
    const int lane = d & 31;

    float U[RANK], Vv[RANK];
#pragma unroll
    for (int r = 0; r < RANK; r++) { U[r] = 0.0f; Vv[r] = 0.0f; }

    __shared__ float red[2][18];

    const size_t strideT = (size_t)N_HEADS * D_HEAD;   // 1024
    size_t idx = ((size_t)b * T * N_HEADS + h) * D_HEAD + d;
    const size_t abase = (size_t)b * T * N_HEADS + h;

    const float inv_sqrt_dh = 0.125f;

    float qt = q[idx], kt = k[idx], vt = v[idx];
    float a  = alpha[abase];

    for (int t = 0; t < T; t++) {
        const size_t nidx = idx + strideT;
        float nq = 0.f, nk = 0.f, nv = 0.f, na = 0.f;
        if (t + 1 < T) {
            nq = q[nidx]; nk = k[nidx]; nv = v[nidx];
            na = alpha[abase + (size_t)(t + 1) * N_HEADS];
        }

        float p[RANK];
#pragma unroll
        for (int r = 0; r < RANK; r++) {
            U[r]  *= DECAY;
            Vv[r] *= DECAY;
            p[r] = kt * U[r];
        }
#pragma unroll
        for (int off = 16; off; off >>= 1)
#pragma unroll
            for (int r = 0; r < RANK; r++)
                p[r] += __shfl_xor_sync(0xFFFFFFFFu, p[r], off);
        if (lane == 0) {
#pragma unroll
            for (int r = 0; r < RANK; r++) red[warp][r] = p[r];
        }
        __syncthreads();
        float ku[RANK];
#pragma unroll
        for (int r = 0; r < RANK; r++) ku[r] = red[0][r] + red[1][r];
        __syncthreads();

        const float ak = a * kt;
        const float av = a * vt;
        float kf = 0.0f;
#pragma unroll
        for (int r = 0; r < RANK; r++) {
            float u = fmaf(ak, ku[r], U[r]);
            float w = fmaf(av, ku[r], Vv[r]);
            u -= BETA * fminf(fmaxf(u, -1.0f), 1.0f);
            w -= BETA * fminf(fmaxf(w, -1.0f), 1.0f);
            U[r] = u;
            Vv[r] = w;
            kf = fmaf(u, w, kf);
        }

        const float qn = qt * inv_sqrt_dh;
        float s0 = qn * kt;
        float s1 = qn * kf;
#pragma unroll
        for (int off = 16; off; off >>= 1) {
            s0 += __shfl_xor_sync(0xFFFFFFFFu, s0, off);
            s1 += __shfl_xor_sync(0xFFFFFFFFu, s1, off);
        }
        if (lane == 0) { red[warp][16] = s0; red[warp][17] = s1; }
        __syncthreads();
        s0 = red[0][16] + red[1][16];
        s1 = red[0][17] + red[1][17];

        const float m1 = 1.0f / (1.0f + expf(s0 - s1));
        const float m0 = 1.0f - m1;

        const float yv = m0 * vt + m1 * kf;
        const __nv_bfloat16 hb = __float2bfloat16(yv);
        yhi[idx] = hb;
        ylo[idx] = __float2bfloat16(yv - __bfloat162float(hb));

        qt = nq; kt = nk; vt = nv; a = na;
        idx = nidx;
    }
}

// ---------------------------------------------------------------------------
// Launch
// ---------------------------------------------------------------------------
extern "C" void kernel_launch(void* const* d_in, const int* in_sizes, int n_in,
                              void* d_out, int out_size)
{
    const float* x      = (const float*)d_in[0];
    const float* m_gate = (const float*)d_in[1];
    const float* ascale = (const float*)d_in[2];
    const float* Wq     = (const float*)d_in[3];
    const float* Wk     = (const float*)d_in[4];
    const float* Wv     = (const float*)d_in[5];
    const float* Wo     = (const float*)d_in[6];
    const float* Wa     = (const float*)d_in[7];
    const float* ba     = (const float*)d_in[8];
    // d_in[9] = mix_logit: cancels in the 2-way softmax; unused.
    float* out = (float*)d_out;

    const int M = in_sizes[1] > 0 ? in_sizes[1] : BT;  // B*T
    const int T = M / BB;

    __nv_bfloat16 *xhi, *xlo, *whi, *wlo, *yhi, *ylo;
    float *dq, *dk, *dv, *da;
    cudaGetSymbolAddress((void**)&xhi, g_xhi);
    cudaGetSymbolAddress((void**)&xlo, g_xlo);
    cudaGetSymbolAddress((void**)&whi, g_whi);
    cudaGetSymbolAddress((void**)&wlo, g_wlo);
    cudaGetSymbolAddress((void**)&yhi, g_yhi);
    cudaGetSymbolAddress((void**)&ylo, g_ylo);
    cudaGetSymbolAddress((void**)&dq, g_q);
    cudaGetSymbolAddress((void**)&dk, g_k);
    cudaGetSymbolAddress((void**)&dv, g_v);
    cudaGetSymbolAddress((void**)&da, g_alpha);

    const int DW = D_MODEL * D_MODEL;

    const int SMEM_BYTES = 4 * TILE_HALVES * 2;   // 73728
    static bool attr_set = false;
    if (!attr_set) {
        cudaFuncSetAttribute(gemm_bf16x2,
                             cudaFuncAttributeMaxDynamicSharedMemorySize, SMEM_BYTES);
        attr_set = true;
    }

    split_kernel<<<(M * D_MODEL + 255) / 256, 256>>>(x, xhi, xlo, M * D_MODEL);
    split_kernel<<<(DW + 255) / 256, 256>>>(Wq, whi + 0 * DW, wlo + 0 * DW, DW);
    split_kernel<<<(DW + 255) / 256, 256>>>(Wk, whi + 1 * DW, wlo + 1 * DW, DW);
    split_kernel<<<(DW + 255) / 256, 256>>>(Wv, whi + 2 * DW, wlo + 2 * DW, DW);
    split_kernel<<<(DW + 255) / 256, 256>>>(Wo, whi + 3 * DW, wlo + 3 * DW, DW);

    dim3 gg(D_MODEL / GN, M / GM);    // (8, 64)
    gemm_bf16x2<<<gg, 256, SMEM_BYTES>>>(xhi, xlo, whi + 0 * DW, wlo + 0 * DW, dq, M, D_MODEL, D_MODEL);
    gemm_bf16x2<<<gg, 256, SMEM_BYTES>>>(xhi, xlo, whi + 1 * DW, wlo + 1 * DW, dk, M, D_MODEL, D_MODEL);
    gemm_bf16x2<<<gg, 256, SMEM_BYTES>>>(xhi, xlo, whi + 2 * DW, wlo + 2 * DW, dv, M, D_MODEL, D_MODEL);

    alpha_kernel<<<M, 256>>>(x, Wa, ba, m_gate, ascale, da);

    scan_kernel<<<BB * N_HEADS, 64>>>(dq, dk, dv, da, yhi, ylo, T);

    gemm_bf16x2<<<gg, 256, SMEM_BYTES>>>(yhi, ylo, whi + 3 * DW, wlo + 3 * DW, out, M, D_MODEL, D_MODEL);
}

// round 4
// speedup vs baseline: 2.5795x; 1.1656x over previous
#include <cuda_runtime.h>
#include <cuda_bf16.h>
#include <math.h>
#include <stdint.h>

// ---------------------------------------------------------------------------
// CortexBlock on GB300 (compute_103 pipeline => mma.sync HMMA path)
// B=4, T=2048, D=1024, H=16, Dh=64, R=16
// GEMMs: bf16x2 error-compensated (hi*hi + hi*lo + lo*hi), fp32 accumulate,
// fused passes: per K-chunk load Ahi/Alo/Bhi/Blo once, run 3 MMA passes.
// ---------------------------------------------------------------------------

#define D_MODEL 1024
#define N_HEADS 16
#define D_HEAD  64
#define RANK    16
#define DECAY   0.95f
#define ALPHA_MAX 0.05f
#define BETA    0.01f

#define BB 4
#define TT 2048
#define BT (BB*TT)   // 8192

// ---------------- scratch (static device globals; no allocs allowed) -------
__device__ __align__(256) __nv_bfloat16 g_xhi[BT * D_MODEL];
__device__ __align__(256) __nv_bfloat16 g_xlo[BT * D_MODEL];
__device__ __align__(256) __nv_bfloat16 g_whi[4 * D_MODEL * D_MODEL];  // Wq,Wk,Wv,Wo
__device__ __align__(256) __nv_bfloat16 g_wlo[4 * D_MODEL * D_MODEL];
__device__ __align__(256) __nv_bfloat16 g_yhi[BT * D_MODEL];
__device__ __align__(256) __nv_bfloat16 g_ylo[BT * D_MODEL];
__device__ __align__(256) float g_q[BT * D_MODEL];
__device__ __align__(256) float g_k[BT * D_MODEL];
__device__ __align__(256) float g_v[BT * D_MODEL];
__device__ __align__(256) float g_alpha[BT * N_HEADS];

// ---------------- small asm helpers ----------------------------------------
__device__ __forceinline__ uint32_t smem_u32(const void* p) {
    uint32_t a;
    asm("{ .reg .u64 t; cvta.to.shared.u64 t, %1; cvt.u32.u64 %0, t; }"
        : "=r"(a) : "l"(p));
    return a;
}
__device__ __forceinline__ void cp_async16(uint32_t daddr, const void* gaddr) {
    asm volatile("cp.async.cg.shared.global [%0], [%1], 16;"
                 :: "r"(daddr), "l"(gaddr) : "memory");
}
#define CP_COMMIT()  asm volatile("cp.async.commit_group;" ::: "memory")
#define CP_WAIT(n)   asm volatile("cp.async.wait_group %0;" :: "n"(n) : "memory")

__device__ __forceinline__ void ldsm_x4(uint32_t (&r)[4], uint32_t addr) {
    asm volatile("ldmatrix.sync.aligned.m8n8.x4.shared.b16 {%0,%1,%2,%3}, [%4];"
                 : "=r"(r[0]), "=r"(r[1]), "=r"(r[2]), "=r"(r[3]) : "r"(addr));
}
__device__ __forceinline__ void mma_16816(float (&d)[4], const uint32_t (&a)[4],
                                          uint32_t b0, uint32_t b1) {
    asm volatile(
        "mma.sync.aligned.m16n8k16.row.col.f32.bf16.bf16.f32 "
        "{%0,%1,%2,%3}, {%4,%5,%6,%7}, {%8,%9}, {%0,%1,%2,%3};"
        : "+f"(d[0]), "+f"(d[1]), "+f"(d[2]), "+f"(d[3])
        : "r"(a[0]), "r"(a[1]), "r"(a[2]), "r"(a[3]), "r"(b0), "r"(b1));
}

// ---------------------------------------------------------------------------
// Fused bf16x2 GEMM: C = Ahi*Bhi^T + Ahi*Blo^T + Alo*Bhi^T  (fp32 out)
// A[M,K], B[N,K] row-major bf16.  CTA tile 128x128, K-chunk 64.
// Per chunk: load 4 tiles (Ahi,Alo,Bhi,Blo) once; 3 MMA passes over them.
// 8 warps = 2(m) x 4(n) of 64x32 warp tiles. 2-stage cp.async pipeline.
// smem row stride 72 halves (144B): conflict-free ldmatrix.
// gridDim.z selects the weight matrix (B = Wbase + z*DW) and output Cz.
// ---------------------------------------------------------------------------
#define GM 128
#define GN 128
#define GKC 64
#define AST 72
#define TILE_HALVES (GM * AST)            // 9216 halves = 18432 B
#define STAGE_HALVES (4 * TILE_HALVES)    // 4 tiles per stage
#define GEMM_SMEM_BYTES (2 * STAGE_HALVES * 2)   // 147456

__global__ __launch_bounds__(256, 1) void gemm_bf16x2(
    const __nv_bfloat16* __restrict__ Ahi, const __nv_bfloat16* __restrict__ Alo,
    const __nv_bfloat16* __restrict__ Whi, const __nv_bfloat16* __restrict__ Wlo,
    float* __restrict__ C0, float* __restrict__ C1, float* __restrict__ C2,
    int M, int N, int K)
{
    extern __shared__ __nv_bfloat16 smem[];

    const int tid  = threadIdx.x;
    const int wid  = tid >> 5;
    const int lane = tid & 31;
    const int rowBase = blockIdx.y * GM;
    const int colBase = blockIdx.x * GN;
    const int z = blockIdx.z;

    const __nv_bfloat16* Bhi = Whi + (size_t)z * D_MODEL * D_MODEL;
    const __nv_bfloat16* Blo = Wlo + (size_t)z * D_MODEL * D_MODEL;
    float* C = (z == 0) ? C0 : (z == 1) ? C1 : C2;

    const int wm = (wid >> 2) * 64;
    const int wn = (wid & 3) * 32;

    const uint32_t smBase = smem_u32(smem);

    float acc[4][4][4];
#pragma unroll
    for (int i = 0; i < 4; i++)
#pragma unroll
        for (int j = 0; j < 4; j++)
#pragma unroll
            for (int c = 0; c < 4; c++) acc[i][j][c] = 0.0f;

    const int aRow = lane & 15;
    const int aKo  = (lane >> 4) * 8;
    const int bNo  = ((lane >> 4) << 3) + (lane & 7);
    const int bKo  = ((lane >> 3) & 1) * 8;

    const int NCH = K / GKC;              // 16

    // issue all 4 tiles for chunk ci into stage buf
    auto issue = [&](int ci, int buf) {
        const int k0 = ci * GKC;
        const uint32_t stage = smBase + (uint32_t)buf * (STAGE_HALVES * 2);
#pragma unroll
        for (int i = 0; i < 4; i++) {
            int L = tid + (i << 8);          // 0..1023
            int row = L >> 3;
            int seg = L & 7;
            uint32_t off = (uint32_t)row * (AST * 2) + seg * 16;
            const size_t ga = (size_t)(rowBase + row) * K + k0 + seg * 8;
            const size_t gb = (size_t)(colBase + row) * K + k0 + seg * 8;
            cp_async16(stage + 0 * (TILE_HALVES * 2) + off, Ahi + ga);
            cp_async16(stage + 1 * (TILE_HALVES * 2) + off, Alo + ga);
            cp_async16(stage + 2 * (TILE_HALVES * 2) + off, Bhi + gb);
            cp_async16(stage + 3 * (TILE_HALVES * 2) + off, Blo + gb);
        }
        CP_COMMIT();
    };

    issue(0, 0);

    for (int ci = 0; ci < NCH; ci++) {
        const int buf = ci & 1;
        __syncthreads();                  // all warps done reading buf^1
        if (ci + 1 < NCH) {
            issue(ci + 1, buf ^ 1);
            CP_WAIT(1);                   // chunk ci arrived
        } else {
            CP_WAIT(0);
        }
        __syncthreads();                  // loads visible to all warps

        const uint32_t stage = smBase + (uint32_t)buf * (STAGE_HALVES * 2);

#pragma unroll
        for (int pass = 0; pass < 3; pass++) {
            const uint32_t aBase = stage + (pass == 2 ? 1u : 0u) * (TILE_HALVES * 2);
            const uint32_t bBase = stage + (pass == 1 ? 3u : 2u) * (TILE_HALVES * 2);
#pragma unroll
            for (int ks = 0; ks < 4; ks++) {
                uint32_t Ar[4][4];
#pragma unroll
                for (int mi = 0; mi < 4; mi++) {
                    uint32_t addr = aBase + (uint32_t)(wm + mi * 16 + aRow) * (AST * 2)
                                  + (uint32_t)(ks * 16 + aKo) * 2;
                    ldsm_x4(Ar[mi], addr);
                }
                uint32_t Br[2][4];
#pragma unroll
                for (int ni = 0; ni < 2; ni++) {
                    uint32_t addr = bBase + (uint32_t)(wn + ni * 16 + bNo) * (AST * 2)
                                  + (uint32_t)(ks * 16 + bKo) * 2;
                    ldsm_x4(Br[ni], addr);
                }
#pragma unroll
                for (int mi = 0; mi < 4; mi++)
#pragma unroll
                    for (int j = 0; j < 4; j++)
                        mma_16816(acc[mi][j], Ar[mi],
                                  Br[j >> 1][(j & 1) * 2], Br[j >> 1][(j & 1) * 2 + 1]);
            }
        }
    }

    // epilogue
#pragma unroll
    for (int mi = 0; mi < 4; mi++) {
        const int row0 = rowBase + wm + mi * 16 + (lane >> 2);
#pragma unroll
        for (int j = 0; j < 4; j++) {
            const int col = colBase + wn + j * 8 + (lane & 3) * 2;
            *reinterpret_cast<float2*>(C + (size_t)row0 * N + col) =
                make_float2(acc[mi][j][0], acc[mi][j][1]);
            *reinterpret_cast<float2*>(C + (size_t)(row0 + 8) * N + col) =
                make_float2(acc[mi][j][2], acc[mi][j][3]);
        }
    }
}

// ---------------------------------------------------------------------------
// fp32 -> (bf16 hi, bf16 lo)
// ---------------------------------------------------------------------------
__global__ __launch_bounds__(256) void split_kernel(
    const float* __restrict__ in, __nv_bfloat16* __restrict__ hi,
    __nv_bfloat16* __restrict__ lo, int n)
{
    int i = blockIdx.x * blockDim.x + threadIdx.x;
    if (i < n) {
        float x = in[i];
        __nv_bfloat16 h = __float2bfloat16(x);
        hi[i] = h;
        lo[i] = __float2bfloat16(x - __bfloat162float(h));
    }
}

// ---------------------------------------------------------------------------
// alpha[row,h] = min( sigmoid(x·Wa[h]+ba[h]) * m_gate * as, ALPHA_MAX )
// ---------------------------------------------------------------------------
__global__ __launch_bounds__(256) void alpha_kernel(
    const float* __restrict__ x, const float* __restrict__ Wa,
    const float* __restrict__ ba, const float* __restrict__ m_gate,
    const float* __restrict__ ascale, float* __restrict__ alpha)
{
    const int row = blockIdx.x;
    const int tid = threadIdx.x;
    const int warp = tid >> 5;
    const int lane = tid & 31;

    __shared__ float4 xs[D_MODEL / 4];
    const float4* xg = reinterpret_cast<const float4*>(x + (size_t)row * D_MODEL);
    for (int i = tid; i < D_MODEL / 4; i += 256) xs[i] = xg[i];
    __syncthreads();

    const float mg = m_gate[row];
#pragma unroll
    for (int hh = 0; hh < 2; hh++) {
        int h = warp + hh * 8;
        const float4* w = reinterpret_cast<const float4*>(Wa + (size_t)h * D_MODEL);
        float s = 0.0f;
        for (int i = lane; i < D_MODEL / 4; i += 32) {
            float4 xv = xs[i];
            float4 wv = w[i];
            s = fmaf(xv.x, wv.x, s);
            s = fmaf(xv.y, wv.y, s);
            s = fmaf(xv.z, wv.z, s);
            s = fmaf(xv.w, wv.w, s);
        }
#pragma unroll
        for (int off = 16; off; off >>= 1)
            s += __shfl_xor_sync(0xFFFFFFFFu, s, off);
        if (lane == 0) {
            float z = s + ba[h];
            float sg = 1.0f / (1.0f + expf(-z));
            float a = sg * mg * ascale[(size_t)row * N_HEADS + h];
            alpha[(size_t)row * N_HEADS + h] = fminf(a, ALPHA_MAX);
        }
    }
}

// ---------------------------------------------------------------------------
// Sequential fast-weight scan; fused y -> bf16x2 output; next-step prefetch.
// Block = (b,h); 64 threads (thread = d).
// ku allreduce: 4-step reduce-scatter in 16-lane groups (compile-time indices)
// + xor-16 combine + cross-warp smem (double-buffered by t parity).
// ---------------------------------------------------------------------------
__global__ __launch_bounds__(64) void scan_kernel(
    const float* __restrict__ q, const float* __restrict__ k,
    const float* __restrict__ v, const float* __restrict__ alpha,
    __nv_bfloat16* __restrict__ yhi, __nv_bfloat16* __restrict__ ylo, int T)
{
    const int bh = blockIdx.x;
    const int b = bh / N_HEADS;
    const int h = bh % N_HEADS;
    const int d = threadIdx.x;
    const int warp = d >> 5;
    const int lane = d & 31;

    float U[RANK], Vv[RANK];
#pragma unroll
    for (int r = 0; r < RANK; r++) { U[r] = 0.0f; Vv[r] = 0.0f; }

    // double-buffered exchange areas
    __shared__ float  sm_ku[2][16][2];   // [buf][r][warp]
    __shared__ float2 sm_sc[2][2];       // [buf][warp] = (s0,s1)

    // r index this lane ends with after reduce-scatter = bitrev4(lane&15)
    const int l4 = lane & 15;
    const int rIdx = ((l4 & 1) << 3) | ((l4 & 2) << 1) | ((l4 & 4) >> 1) | ((l4 & 8) >> 3);

    const size_t strideT = (size_t)N_HEADS * D_HEAD;   // 1024
    size_t idx = ((size_t)b * T * N_HEADS + h) * D_HEAD + d;
    const size_t abase = (size_t)b * T * N_HEADS + h;

    const float inv_sqrt_dh = 0.125f;

    float qt = q[idx], kt = k[idx], vt = v[idx];
    float a  = alpha[abase];

    for (int t = 0; t < T; t++) {
        const int buf = t & 1;
        const size_t nidx = idx + strideT;
        float nq = 0.f, nk = 0.f, nv = 0.f, na = 0.f;
        if (t + 1 < T) {
            nq = q[nidx]; nk = k[nidx]; nv = v[nidx];
            na = alpha[abase + (size_t)(t + 1) * N_HEADS];
        }

        // decay + ku partials
        float p[RANK];
#pragma unroll
        for (int r = 0; r < RANK; r++) {
            U[r]  *= DECAY;
            Vv[r] *= DECAY;
            p[r] = kt * U[r];
        }

        // 4-step reduce-scatter within 16-lane groups (compaction keeps indices
        // compile-time). After this, p[0] = sum over 16-lane group for r=rIdx.
#pragma unroll
        for (int s = 1, cnt = 8; s <= 8; s <<= 1, cnt >>= 1) {
            const bool hi = (lane & s) != 0;
#pragma unroll
            for (int i = 0; i < cnt; i++) {
                float lo_v = p[i], hi_v = p[i + cnt];
                float send = hi ? lo_v : hi_v;
                float recv = __shfl_xor_sync(0xFFFFFFFFu, send, s);
                p[i] = (hi ? hi_v : lo_v) + recv;
            }
        }
        // combine the two 16-lane groups of this warp
        float vr = p[0] + __shfl_xor_sync(0xFFFFFFFFu, p[0], 16);
        // cross-warp via smem (lanes 0-15 and 16-31 write same value: benign)
        sm_ku[buf][rIdx][warp] = vr;
        __syncthreads();

        float ku[RANK];
#pragma unroll
        for (int r = 0; r < RANK; r++) {
            float2 t2 = *reinterpret_cast<const float2*>(&sm_ku[buf][r][0]);
            ku[r] = t2.x + t2.y;
        }

        const float ak = a * kt;
        const float av = a * vt;
        float kf = 0.0f;
#pragma unroll
        for (int r = 0; r < RANK; r++) {
            float u = fmaf(ak, ku[r], U[r]);
            float w = fmaf(av, ku[r], Vv[r]);
            u -= BETA * fminf(fmaxf(u, -1.0f), 1.0f);
            w -= BETA * fminf(fmaxf(w, -1.0f), 1.0f);
            U[r] = u;
            Vv[r] = w;
            kf = fmaf(u, w, kf);
        }

        const float qn = qt * inv_sqrt_dh;
        float s0 = qn * kt;
        float s1 = qn * kf;
#pragma unroll
        for (int off = 16; off; off >>= 1) {
            s0 += __shfl_xor_sync(0xFFFFFFFFu, s0, off);
            s1 += __shfl_xor_sync(0xFFFFFFFFu, s1, off);
        }
        if (lane == 0) sm_sc[buf][warp] = make_float2(s0, s1);
        __syncthreads();
        {
            float2 w0 = sm_sc[buf][0];
            float2 w1 = sm_sc[buf][1];
            s0 = w0.x + w1.x;
            s1 = w0.y + w1.y;
        }

        const float m1 = 1.0f / (1.0f + expf(s0 - s1));
        const float m0 = 1.0f - m1;

        const float yv = m0 * vt + m1 * kf;
        const __nv_bfloat16 hb = __float2bfloat16(yv);
        yhi[idx] = hb;
        ylo[idx] = __float2bfloat16(yv - __bfloat162float(hb));

        qt = nq; kt = nk; vt = nv; a = na;
        idx = nidx;
    }
}

// ---------------------------------------------------------------------------
// Launch
// ---------------------------------------------------------------------------
extern "C" void kernel_launch(void* const* d_in, const int* in_sizes, int n_in,
                              void* d_out, int out_size)
{
    const float* x      = (const float*)d_in[0];
    const float* m_gate = (const float*)d_in[1];
    const float* ascale = (const float*)d_in[2];
    const float* Wq     = (const float*)d_in[3];
    const float* Wk     = (const float*)d_in[4];
    const float* Wv     = (const float*)d_in[5];
    const float* Wo     = (const float*)d_in[6];
    const float* Wa     = (const float*)d_in[7];
    const float* ba     = (const float*)d_in[8];
    // d_in[9] = mix_logit: cancels in the 2-way softmax; unused.
    float* out = (float*)d_out;

    const int M = in_sizes[1] > 0 ? in_sizes[1] : BT;  // B*T
    const int T = M / BB;

    __nv_bfloat16 *xhi, *xlo, *whi, *wlo, *yhi, *ylo;
    float *dq, *dk, *dv, *da;
    cudaGetSymbolAddress((void**)&xhi, g_xhi);
    cudaGetSymbolAddress((void**)&xlo, g_xlo);
    cudaGetSymbolAddress((void**)&whi, g_whi);
    cudaGetSymbolAddress((void**)&wlo, g_wlo);
    cudaGetSymbolAddress((void**)&yhi, g_yhi);
    cudaGetSymbolAddress((void**)&ylo, g_ylo);
    cudaGetSymbolAddress((void**)&dq, g_q);
    cudaGetSymbolAddress((void**)&dk, g_k);
    cudaGetSymbolAddress((void**)&dv, g_v);
    cudaGetSymbolAddress((void**)&da, g_alpha);

    const int DW = D_MODEL * D_MODEL;

    static bool attr_set = false;
    if (!attr_set) {
        cudaFuncSetAttribute(gemm_bf16x2,
                             cudaFuncAttributeMaxDynamicSharedMemorySize, GEMM_SMEM_BYTES);
        attr_set = true;
    }

    split_kernel<<<(M * D_MODEL + 255) / 256, 256>>>(x, xhi, xlo, M * D_MODEL);
    split_kernel<<<(DW + 255) / 256, 256>>>(Wq, whi + 0 * DW, wlo + 0 * DW, DW);
    split_kernel<<<(DW + 255) / 256, 256>>>(Wk, whi + 1 * DW, wlo + 1 * DW, DW);
    split_kernel<<<(DW + 255) / 256, 256>>>(Wv, whi + 2 * DW, wlo + 2 * DW, DW);
    split_kernel<<<(DW + 255) / 256, 256>>>(Wo, whi + 3 * DW, wlo + 3 * DW, DW);

    // QKV fused: gridDim.z = 3 selects weight/output
    dim3 gqkv(D_MODEL / GN, M / GM, 3);
    gemm_bf16x2<<<gqkv, 256, GEMM_SMEM_BYTES>>>(xhi, xlo, whi, wlo,
                                                dq, dk, dv, M, D_MODEL, D_MODEL);

    alpha_kernel<<<M, 256>>>(x, Wa, ba, m_gate, ascale, da);

    scan_kernel<<<BB * N_HEADS, 64>>>(dq, dk, dv, da, yhi, ylo, T);

    // output projection (z=0 -> C0=out, B = whi+3*DW)
    dim3 go(D_MODEL / GN, M / GM, 1);
    gemm_bf16x2<<<go, 256, GEMM_SMEM_BYTES>>>(yhi, ylo, whi + 3 * DW, wlo + 3 * DW,
                                              out, out, out, M, D_MODEL, D_MODEL);
}

// round 5
// speedup vs baseline: 2.5942x; 1.0057x over previous
#include <cuda_runtime.h>
#include <cuda_bf16.h>
#include <math.h>
#include <stdint.h>

// ---------------------------------------------------------------------------
// CortexBlock on GB300 (compute_103 pipeline => mma.sync HMMA path)
// B=4, T=2048, D=1024, H=16, Dh=64, R=16
// GEMMs: bf16x2 error-compensated (hi*hi + hi*lo + lo*hi), fp32 accumulate.
// 3-stage cp.async pipeline, 1 barrier per K-chunk.
// Scan: 1 barrier per step (score exchange piggybacked on next step's barrier).
// ---------------------------------------------------------------------------

#define D_MODEL 1024
#define N_HEADS 16
#define D_HEAD  64
#define RANK    16
#define DECAY   0.95f
#define ALPHA_MAX 0.05f
#define BETA    0.01f

#define BB 4
#define TT 2048
#define BT (BB*TT)   // 8192

// ---------------- scratch (static device globals; no allocs allowed) -------
__device__ __align__(256) __nv_bfloat16 g_xhi[BT * D_MODEL];
__device__ __align__(256) __nv_bfloat16 g_xlo[BT * D_MODEL];
__device__ __align__(256) __nv_bfloat16 g_whi[4 * D_MODEL * D_MODEL];  // Wq,Wk,Wv,Wo
__device__ __align__(256) __nv_bfloat16 g_wlo[4 * D_MODEL * D_MODEL];
__device__ __align__(256) __nv_bfloat16 g_yhi[BT * D_MODEL];
__device__ __align__(256) __nv_bfloat16 g_ylo[BT * D_MODEL];
__device__ __align__(256) float g_q[BT * D_MODEL];
__device__ __align__(256) float g_k[BT * D_MODEL];
__device__ __align__(256) float g_v[BT * D_MODEL];
__device__ __align__(256) float g_alpha[BT * N_HEADS];

// ---------------- small asm helpers ----------------------------------------
__device__ __forceinline__ uint32_t smem_u32(const void* p) {
    uint32_t a;
    asm("{ .reg .u64 t; cvta.to.shared.u64 t, %1; cvt.u32.u64 %0, t; }"
        : "=r"(a) : "l"(p));
    return a;
}
__device__ __forceinline__ void cp_async16(uint32_t daddr, const void* gaddr) {
    asm volatile("cp.async.cg.shared.global [%0], [%1], 16;"
                 :: "r"(daddr), "l"(gaddr) : "memory");
}
#define CP_COMMIT()  asm volatile("cp.async.commit_group;" ::: "memory")
#define CP_WAIT(n)   asm volatile("cp.async.wait_group %0;" :: "n"(n) : "memory")

__device__ __forceinline__ void ldsm_x4(uint32_t (&r)[4], uint32_t addr) {
    asm volatile("ldmatrix.sync.aligned.m8n8.x4.shared.b16 {%0,%1,%2,%3}, [%4];"
                 : "=r"(r[0]), "=r"(r[1]), "=r"(r[2]), "=r"(r[3]) : "r"(addr));
}
__device__ __forceinline__ void mma_16816(float (&d)[4], const uint32_t (&a)[4],
                                          uint32_t b0, uint32_t b1) {
    asm volatile(
        "mma.sync.aligned.m16n8k16.row.col.f32.bf16.bf16.f32 "
        "{%0,%1,%2,%3}, {%4,%5,%6,%7}, {%8,%9}, {%0,%1,%2,%3};"
        : "+f"(d[0]), "+f"(d[1]), "+f"(d[2]), "+f"(d[3])
        : "r"(a[0]), "r"(a[1]), "r"(a[2]), "r"(a[3]), "r"(b0), "r"(b1));
}

// ---------------------------------------------------------------------------
// Fused bf16x2 GEMM: C = Ahi*Bhi^T + Ahi*Blo^T + Alo*Bhi^T  (fp32 out)
// CTA tile 128x128, K-chunk 64. Per chunk: 4 tiles (Ahi,Alo,Bhi,Blo) loaded
// once; 3 MMA passes. 8 warps = 2(m) x 4(n) of 64x32 warp tiles.
// 3-stage cp.async pipeline, ONE __syncthreads per chunk.
// ---------------------------------------------------------------------------
#define GM 128
#define GN 128
#define GKC 64
#define AST 72
#define TILE_HALVES (GM * AST)            // 9216 halves = 18432 B
#define STAGE_HALVES (4 * TILE_HALVES)    // 4 tiles per stage = 73728 B
#define STAGE_BYTES (STAGE_HALVES * 2)
#define GEMM_SMEM_BYTES (3 * STAGE_BYTES) // 221184

__global__ __launch_bounds__(256, 1) void gemm_bf16x2(
    const __nv_bfloat16* __restrict__ Ahi, const __nv_bfloat16* __restrict__ Alo,
    const __nv_bfloat16* __restrict__ Whi, const __nv_bfloat16* __restrict__ Wlo,
    float* __restrict__ C0, float* __restrict__ C1, float* __restrict__ C2,
    int M, int N, int K)
{
    extern __shared__ __nv_bfloat16 smem[];

    const int tid  = threadIdx.x;
    const int wid  = tid >> 5;
    const int lane = tid & 31;
    const int rowBase = blockIdx.y * GM;
    const int colBase = blockIdx.x * GN;
    const int z = blockIdx.z;

    const __nv_bfloat16* Bhi = Whi + (size_t)z * D_MODEL * D_MODEL;
    const __nv_bfloat16* Blo = Wlo + (size_t)z * D_MODEL * D_MODEL;
    float* C = (z == 0) ? C0 : (z == 1) ? C1 : C2;

    const int wm = (wid >> 2) * 64;
    const int wn = (wid & 3) * 32;

    const uint32_t smBase = smem_u32(smem);

    float acc[4][4][4];
#pragma unroll
    for (int i = 0; i < 4; i++)
#pragma unroll
        for (int j = 0; j < 4; j++)
#pragma unroll
            for (int c = 0; c < 4; c++) acc[i][j][c] = 0.0f;

    const int aRow = lane & 15;
    const int aKo  = (lane >> 4) * 8;
    const int bNo  = ((lane >> 4) << 3) + (lane & 7);
    const int bKo  = ((lane >> 3) & 1) * 8;

    const int NCH = K / GKC;              // 16

    auto issue = [&](int ci) {
        const int k0 = ci * GKC;
        const uint32_t stage = smBase + (uint32_t)(ci % 3) * STAGE_BYTES;
#pragma unroll
        for (int i = 0; i < 4; i++) {
            int L = tid + (i << 8);
            int row = L >> 3;
            int seg = L & 7;
            uint32_t off = (uint32_t)row * (AST * 2) + seg * 16;
            const size_t ga = (size_t)(rowBase + row) * K + k0 + seg * 8;
            const size_t gb = (size_t)(colBase + row) * K + k0 + seg * 8;
            cp_async16(stage + 0 * (TILE_HALVES * 2) + off, Ahi + ga);
            cp_async16(stage + 1 * (TILE_HALVES * 2) + off, Alo + ga);
            cp_async16(stage + 2 * (TILE_HALVES * 2) + off, Bhi + gb);
            cp_async16(stage + 3 * (TILE_HALVES * 2) + off, Blo + gb);
        }
        CP_COMMIT();
    };

    issue(0);
    issue(1);

    for (int ci = 0; ci < NCH; ci++) {
        CP_WAIT(1);                       // chunk ci complete (per thread)
        __syncthreads();                  // visibility + buffer-reuse safety
        if (ci + 2 < NCH) issue(ci + 2);  // into buf (ci+2)%3 (read done at ci-1)
        else CP_COMMIT();                 // empty group keeps wait(1) semantics

        const uint32_t stage = smBase + (uint32_t)(ci % 3) * STAGE_BYTES;

#pragma unroll
        for (int pass = 0; pass < 3; pass++) {
            const uint32_t aBase = stage + (pass == 2 ? 1u : 0u) * (TILE_HALVES * 2);
            const uint32_t bBase = stage + (pass == 1 ? 3u : 2u) * (TILE_HALVES * 2);
#pragma unroll
            for (int ks = 0; ks < 4; ks++) {
                uint32_t Ar[4][4];
#pragma unroll
                for (int mi = 0; mi < 4; mi++) {
                    uint32_t addr = aBase + (uint32_t)(wm + mi * 16 + aRow) * (AST * 2)
                                  + (uint32_t)(ks * 16 + aKo) * 2;
                    ldsm_x4(Ar[mi], addr);
                }
                uint32_t Br[2][4];
#pragma unroll
                for (int ni = 0; ni < 2; ni++) {
                    uint32_t addr = bBase + (uint32_t)(wn + ni * 16 + bNo) * (AST * 2)
                                  + (uint32_t)(ks * 16 + bKo) * 2;
                    ldsm_x4(Br[ni], addr);
                }
#pragma unroll
                for (int mi = 0; mi < 4; mi++)
#pragma unroll
                    for (int j = 0; j < 4; j++)
                        mma_16816(acc[mi][j], Ar[mi],
                                  Br[j >> 1][(j & 1) * 2], Br[j >> 1][(j & 1) * 2 + 1]);
            }
        }
    }

    // epilogue
#pragma unroll
    for (int mi = 0; mi < 4; mi++) {
        const int row0 = rowBase + wm + mi * 16 + (lane >> 2);
#pragma unroll
        for (int j = 0; j < 4; j++) {
            const int col = colBase + wn + j * 8 + (lane & 3) * 2;
            *reinterpret_cast<float2*>(C + (size_t)row0 * N + col) =
                make_float2(acc[mi][j][0], acc[mi][j][1]);
            *reinterpret_cast<float2*>(C + (size_t)(row0 + 8) * N + col) =
                make_float2(acc[mi][j][2], acc[mi][j][3]);
        }
    }
}

// ---------------------------------------------------------------------------
// Fused x-split + alpha. Block = 16 rows, 512 threads (16 warps = 16 heads).
// Wa row cached in registers (32 f/lane); x rows staged in smem (fp32).
// ---------------------------------------------------------------------------
__global__ __launch_bounds__(512) void splitx_alpha_kernel(
    const float* __restrict__ x, const float* __restrict__ Wa,
    const float* __restrict__ ba, const float* __restrict__ m_gate,
    const float* __restrict__ ascale,
    __nv_bfloat16* __restrict__ xhi, __nv_bfloat16* __restrict__ xlo,
    float* __restrict__ alpha)
{
    extern __shared__ float xs[];        // [16][1024]
    const int tid  = threadIdx.x;
    const int warp = tid >> 5;           // head
    const int lane = tid & 31;
    const int rowBase = blockIdx.x * 16;

    // load + split (float4 granularity: 4096 per block)
    const float4* xg = reinterpret_cast<const float4*>(x + (size_t)rowBase * D_MODEL);
#pragma unroll
    for (int it = 0; it < 8; it++) {
        int i = tid + it * 512;
        float4 v = xg[i];
        reinterpret_cast<float4*>(xs)[i] = v;
        __nv_bfloat16 h0 = __float2bfloat16(v.x);
        __nv_bfloat16 h1 = __float2bfloat16(v.y);
        __nv_bfloat16 h2 = __float2bfloat16(v.z);
        __nv_bfloat16 h3 = __float2bfloat16(v.w);
        __nv_bfloat162* ph = reinterpret_cast<__nv_bfloat162*>(
            xhi + (size_t)rowBase * D_MODEL + i * 4);
        __nv_bfloat162* pl = reinterpret_cast<__nv_bfloat162*>(
            xlo + (size_t)rowBase * D_MODEL + i * 4);
        ph[0] = __nv_bfloat162(h0, h1);
        ph[1] = __nv_bfloat162(h2, h3);
        pl[0] = __nv_bfloat162(__float2bfloat16(v.x - __bfloat162float(h0)),
                               __float2bfloat16(v.y - __bfloat162float(h1)));
        pl[1] = __nv_bfloat162(__float2bfloat16(v.z - __bfloat162float(h2)),
                               __float2bfloat16(v.w - __bfloat162float(h3)));
    }
    __syncthreads();

    // Wa row for this head in registers: wa[i] = Wa[warp][i*32+lane]
    float wa[32];
#pragma unroll
    for (int i = 0; i < 32; i++)
        wa[i] = Wa[(size_t)warp * D_MODEL + i * 32 + lane];
    const float bw = ba[warp];

#pragma unroll 4
    for (int row = 0; row < 16; row++) {
        const float* xr = xs + row * D_MODEL;
        float s = 0.0f;
#pragma unroll
        for (int i = 0; i < 32; i++)
            s = fmaf(wa[i], xr[i * 32 + lane], s);
#pragma unroll
        for (int off = 16; off; off >>= 1)
            s += __shfl_xor_sync(0xFFFFFFFFu, s, off);
        if (lane == 0) {
            const int r = rowBase + row;
            float sg = __fdividef(1.0f, 1.0f + __expf(-(s + bw)));
            float a = sg * m_gate[r] * ascale[(size_t)r * N_HEADS + warp];
            alpha[(size_t)r * N_HEADS + warp] = fminf(a, ALPHA_MAX);
        }
    }
}

// ---------------------------------------------------------------------------
// Weight splits, all 4 matrices in one launch. DW = 1<<20 elements each.
// ---------------------------------------------------------------------------
__global__ __launch_bounds__(256) void split4_kernel(
    const float* __restrict__ W0, const float* __restrict__ W1,
    const float* __restrict__ W2, const float* __restrict__ W3,
    __nv_bfloat16* __restrict__ hi, __nv_bfloat16* __restrict__ lo)
{
    const int i = blockIdx.x * 256 + threadIdx.x;       // 0 .. 4M-1
    const int sel = i >> 20;
    const int off = i & ((1 << 20) - 1);
    const float* src = (sel == 0) ? W0 : (sel == 1) ? W1 : (sel == 2) ? W2 : W3;
    float v = src[off];
    __nv_bfloat16 h = __float2bfloat16(v);
    hi[i] = h;
    lo[i] = __float2bfloat16(v - __bfloat162float(h));
}

// ---------------------------------------------------------------------------
// Sequential fast-weight scan; 1 barrier/step (score combine of step t-1 is
// piggybacked on step t's barrier; y(t-1) stored during step t).
// Block = (b,h); 64 threads (thread = d).
// ---------------------------------------------------------------------------
__global__ __launch_bounds__(64) void scan_kernel(
    const float* __restrict__ q, const float* __restrict__ k,
    const float* __restrict__ v, const float* __restrict__ alpha,
    __nv_bfloat16* __restrict__ yhi, __nv_bfloat16* __restrict__ ylo, int T)
{
    const int bh = blockIdx.x;
    const int b = bh / N_HEADS;
    const int h = bh % N_HEADS;
    const int d = threadIdx.x;
    const int warp = d >> 5;
    const int lane = d & 31;

    float U[RANK], Vv[RANK];
#pragma unroll
    for (int r = 0; r < RANK; r++) { U[r] = 0.0f; Vv[r] = 0.0f; }

    __shared__ float  sm_ku[2][16][2];   // [buf][r][warp]
    __shared__ float2 sm_sc[2][2];       // [buf][warp] = (s0,s1) partials

    const int l4 = lane & 15;
    const int rIdx = ((l4 & 1) << 3) | ((l4 & 2) << 1) | ((l4 & 4) >> 1) | ((l4 & 8) >> 3);

    const size_t strideT = (size_t)N_HEADS * D_HEAD;   // 1024
    size_t idx = ((size_t)b * T * N_HEADS + h) * D_HEAD + d;
    const size_t abase = (size_t)b * T * N_HEADS + h;

    float qt = q[idx], kt = k[idx], vt = v[idx];
    float a  = alpha[abase];

    float sp0 = 0.f, sp1 = 0.f;     // warp score partials of step t-1
    float vprev = 0.f, kfprev = 0.f;
    size_t idxprev = idx;

    for (int t = 0; t < T; t++) {
        const int buf = t & 1;
        const size_t nidx = idx + strideT;
        float nq = 0.f, nk = 0.f, nv = 0.f, na = 0.f;
        if (t + 1 < T) {
            nq = q[nidx]; nk = k[nidx]; nv = v[nidx];
            na = alpha[abase + (size_t)(t + 1) * N_HEADS];
        }

        // decay + ku partials
        float p[RANK];
#pragma unroll
        for (int r = 0; r < RANK; r++) {
            U[r]  *= DECAY;
            Vv[r] *= DECAY;
            p[r] = kt * U[r];
        }

        // reduce-scatter within 16-lane groups (compile-time compaction)
#pragma unroll
        for (int s = 1, cnt = 8; s <= 8; s <<= 1, cnt >>= 1) {
            const bool hi = (lane & s) != 0;
#pragma unroll
            for (int i = 0; i < cnt; i++) {
                float lo_v = p[i], hi_v = p[i + cnt];
                float send = hi ? lo_v : hi_v;
                float recv = __shfl_xor_sync(0xFFFFFFFFu, send, s);
                p[i] = (hi ? hi_v : lo_v) + recv;
            }
        }
        float vr = p[0] + __shfl_xor_sync(0xFFFFFFFFu, p[0], 16);

        sm_ku[buf][rIdx][warp] = vr;
        if (lane == 0) sm_sc[buf][warp] = make_float2(sp0, sp1);
        __syncthreads();                  // the ONLY barrier this step

        float ku[RANK];
#pragma unroll
        for (int r = 0; r < RANK; r++) {
            float2 t2 = *reinterpret_cast<const float2*>(&sm_ku[buf][r][0]);
            ku[r] = t2.x + t2.y;
        }

        const float ak = a * kt;
        const float av = a * vt;
        float kf = 0.0f;
#pragma unroll
        for (int r = 0; r < RANK; r++) {
            float u = fmaf(ak, ku[r], U[r]);
            float w = fmaf(av, ku[r], Vv[r]);
            u -= BETA * fminf(fmaxf(u, -1.0f), 1.0f);
            w -= BETA * fminf(fmaxf(w, -1.0f), 1.0f);
            U[r] = u;
            Vv[r] = w;
            kf = fmaf(u, w, kf);
        }

        // finalize y(t-1) (off the state critical path)
        if (t > 0) {
            float2 w0 = sm_sc[buf][0];
            float2 w1 = sm_sc[buf][1];
            const float S0 = w0.x + w1.x;
            const float S1 = w0.y + w1.y;
            const float m1 = __fdividef(1.0f, 1.0f + __expf(S0 - S1));
            const float yv = (1.0f - m1) * vprev + m1 * kfprev;
            const __nv_bfloat16 hb = __float2bfloat16(yv);
            yhi[idxprev] = hb;
            ylo[idxprev] = __float2bfloat16(yv - __bfloat162float(hb));
        }

        // this step's score partials (warp butterfly; combined next barrier)
        const float qn = qt * 0.125f;
        float s0 = qn * kt;
        float s1 = qn * kf;
#pragma unroll
        for (int off = 16; off; off >>= 1) {
            s0 += __shfl_xor_sync(0xFFFFFFFFu, s0, off);
            s1 += __shfl_xor_sync(0xFFFFFFFFu, s1, off);
        }
        sp0 = s0; sp1 = s1;
        vprev = vt; kfprev = kf; idxprev = idx;

        qt = nq; kt = nk; vt = nv; a = na;
        idx = nidx;
    }

    // tail: combine scores of step T-1 and store its y
    if (lane == 0) sm_sc[T & 1][warp] = make_float2(sp0, sp1);
    __syncthreads();
    {
        float2 w0 = sm_sc[T & 1][0];
        float2 w1 = sm_sc[T & 1][1];
        const float S0 = w0.x + w1.x;
        const float S1 = w0.y + w1.y;
        const float m1 = __fdividef(1.0f, 1.0f + __expf(S0 - S1));
        const float yv = (1.0f - m1) * vprev + m1 * kfprev;
        const __nv_bfloat16 hb = __float2bfloat16(yv);
        yhi[idxprev] = hb;
        ylo[idxprev] = __float2bfloat16(yv - __bfloat162float(hb));
    }
}

// ---------------------------------------------------------------------------
// Launch
// ---------------------------------------------------------------------------
extern "C" void kernel_launch(void* const* d_in, const int* in_sizes, int n_in,
                              void* d_out, int out_size)
{
    const float* x      = (const float*)d_in[0];
    const float* m_gate = (const float*)d_in[1];
    const float* ascale = (const float*)d_in[2];
    const float* Wq     = (const float*)d_in[3];
    const float* Wk     = (const float*)d_in[4];
    const float* Wv     = (const float*)d_in[5];
    const float* Wo     = (const float*)d_in[6];
    const float* Wa     = (const float*)d_in[7];
    const float* ba     = (const float*)d_in[8];
    // d_in[9] = mix_logit: cancels in the 2-way softmax; unused.
    float* out = (float*)d_out;

    const int M = in_sizes[1] > 0 ? in_sizes[1] : BT;  // B*T
    const int T = M / BB;

    __nv_bfloat16 *xhi, *xlo, *whi, *wlo, *yhi, *ylo;
    float *dq, *dk, *dv, *da;
    cudaGetSymbolAddress((void**)&xhi, g_xhi);
    cudaGetSymbolAddress((void**)&xlo, g_xlo);
    cudaGetSymbolAddress((void**)&whi, g_whi);
    cudaGetSymbolAddress((void**)&wlo, g_wlo);
    cudaGetSymbolAddress((void**)&yhi, g_yhi);
    cudaGetSymbolAddress((void**)&ylo, g_ylo);
    cudaGetSymbolAddress((void**)&dq, g_q);
    cudaGetSymbolAddress((void**)&dk, g_k);
    cudaGetSymbolAddress((void**)&dv, g_v);
    cudaGetSymbolAddress((void**)&da, g_alpha);

    const int DW = D_MODEL * D_MODEL;

    static bool attr_set = false;
    if (!attr_set) {
        cudaFuncSetAttribute(gemm_bf16x2,
                             cudaFuncAttributeMaxDynamicSharedMemorySize, GEMM_SMEM_BYTES);
        cudaFuncSetAttribute(splitx_alpha_kernel,
                             cudaFuncAttributeMaxDynamicSharedMemorySize, 16 * D_MODEL * 4);
        attr_set = true;
    }

    // fused x-split + alpha (512 blocks of 16 rows)
    splitx_alpha_kernel<<<M / 16, 512, 16 * D_MODEL * 4>>>(
        x, Wa, ba, m_gate, ascale, xhi, xlo, da);

    // all 4 weight splits in one launch
    split4_kernel<<<(4 * DW) / 256, 256>>>(Wq, Wk, Wv, Wo, whi, wlo);

    // QKV fused: gridDim.z = 3 selects weight/output
    dim3 gqkv(D_MODEL / GN, M / GM, 3);
    gemm_bf16x2<<<gqkv, 256, GEMM_SMEM_BYTES>>>(xhi, xlo, whi, wlo,
                                                dq, dk, dv, M, D_MODEL, D_MODEL);

    scan_kernel<<<BB * N_HEADS, 64>>>(dq, dk, dv, da, yhi, ylo, T);

    // output projection
    dim3 go(D_MODEL / GN, M / GM, 1);
    gemm_bf16x2<<<go, 256, GEMM_SMEM_BYTES>>>(yhi, ylo, whi + 3 * DW, wlo + 3 * DW,
                                              out, out, out, M, D_MODEL, D_MODEL);
}